// round 2
// baseline (speedup 1.0000x reference)
#include <cuda_runtime.h>

#define TB      16
#define THREADS 256
#define NAG     32
#define SDIM    512
#define HDIM    64
#define N1      32
#define N2      496
#define NF      528
#define PAD     20   // row-padded transposed tiles: 16 rows + 4 pad (STS 4-way max, LDS.128-aligned)

__device__ __forceinline__ float elu_f(float x) {
    return x > 0.f ? x : (__expf(x) - 1.f);
}

__global__ __launch_bounds__(THREADS) void na2q_kernel(
    const float* __restrict__ q_in,   const float* __restrict__ state,  const float* __restrict__ sem,
    const float* __restrict__ w1_1,   const float* __restrict__ b1_1,
    const float* __restrict__ w2_1,   const float* __restrict__ b2_1,
    const float* __restrict__ w3_1,   const float* __restrict__ b3_1,
    const float* __restrict__ w1_2,   const float* __restrict__ b1_2,
    const float* __restrict__ w2_2,   const float* __restrict__ b2_2,
    const float* __restrict__ w3_2,   const float* __restrict__ b3_2,
    const float* __restrict__ ws_w,   const float* __restrict__ ws_b,
    const float* __restrict__ wz_w,   const float* __restrict__ wz_b,
    const float* __restrict__ wa1_w,  const float* __restrict__ wa1_b,
    const float* __restrict__ wa2_w,  const float* __restrict__ wa2_b,
    const float* __restrict__ wb1_w,  const float* __restrict__ wb1_b,
    const float* __restrict__ wb2_w,  const float* __restrict__ wb2_b,
    float* __restrict__ out_q, float* __restrict__ out_attn, float* __restrict__ out_shape)
{
    extern __shared__ float sm[];
    float* s_xt    = sm;                         // SDIM*PAD   (transposed state, then sem)
    float* s_comb  = s_xt   + SDIM * PAD;        // 128*PAD    (combined enc, transposed [k][r])
    float* s_a1    = s_comb + 2 * HDIM * PAD;    // 64*PAD     (a1, transposed [k][r])
    float* s_attn  = s_a1   + HDIM * PAD;        // TB*NF      (logits -> attn weights)
    float* s_shape = s_attn + TB * NF;           // TB*NF
    float* s_q     = s_shape + TB * NF;          // TB*NAG
    float* s_bias  = s_q    + TB * NAG;          // TB

    const int tid  = threadIdx.x;
    const int row0 = blockIdx.x * TB;
    const int h    = tid & 63;
    const int g    = tid >> 6;
    const int r0   = g * 4;
    const int warp = tid >> 5;
    const int lane = tid & 31;

    // ---- stage 1: load q tile, state tile (transposed), init bias acc ----
    for (int i = tid; i < TB * NAG; i += THREADS) s_q[i] = q_in[row0 * NAG + i];
    if (tid < TB) s_bias[tid] = wb2_b[0];
    for (int i = tid; i < TB * SDIM; i += THREADS) {
        int r = i >> 9, k = i & 511;
        s_xt[k * PAD + r] = state[(row0 + r) * SDIM + k];
    }
    __syncthreads();

    // ---- stage 2: fused GEMVs  state_enc = relu(state@ws_w+b)  and bias-net hidden ----
    {
        float bs = ws_b[h], bb = wb1_b[h];
        float aS0 = bs, aS1 = bs, aS2 = bs, aS3 = bs;
        float aB0 = bb, aB1 = bb, aB2 = bb, aB3 = bb;
        #pragma unroll 4
        for (int k = 0; k < SDIM; k++) {
            float w  = ws_w [k * HDIM + h];
            float wB = wb1_w[k * HDIM + h];
            float4 x = *(const float4*)(s_xt + k * PAD + r0);
            aS0 = fmaf(w,  x.x, aS0); aS1 = fmaf(w,  x.y, aS1);
            aS2 = fmaf(w,  x.z, aS2); aS3 = fmaf(w,  x.w, aS3);
            aB0 = fmaf(wB, x.x, aB0); aB1 = fmaf(wB, x.y, aB1);
            aB2 = fmaf(wB, x.z, aB2); aB3 = fmaf(wB, x.w, aB3);
        }
        s_comb[h * PAD + r0 + 0] = fmaxf(aS0, 0.f);
        s_comb[h * PAD + r0 + 1] = fmaxf(aS1, 0.f);
        s_comb[h * PAD + r0 + 2] = fmaxf(aS2, 0.f);
        s_comb[h * PAD + r0 + 3] = fmaxf(aS3, 0.f);
        float wb2h = wb2_w[h];
        atomicAdd(&s_bias[r0 + 0], fmaxf(aB0, 0.f) * wb2h);
        atomicAdd(&s_bias[r0 + 1], fmaxf(aB1, 0.f) * wb2h);
        atomicAdd(&s_bias[r0 + 2], fmaxf(aB2, 0.f) * wb2h);
        atomicAdd(&s_bias[r0 + 3], fmaxf(aB3, 0.f) * wb2h);
    }
    __syncthreads();

    // ---- stage 3: load semantics tile (transposed), overwrite s_xt ----
    for (int i = tid; i < TB * SDIM; i += THREADS) {
        int r = i >> 9, k = i & 511;
        s_xt[k * PAD + r] = sem[(row0 + r) * SDIM + k];
    }
    __syncthreads();

    // ---- stage 4: sem_enc = relu(sem_flat@wz_w+b) ----
    {
        float bz = wz_b[h];
        float a0 = bz, a1 = bz, a2 = bz, a3 = bz;
        #pragma unroll 4
        for (int k = 0; k < SDIM; k++) {
            float w  = wz_w[k * HDIM + h];
            float4 x = *(const float4*)(s_xt + k * PAD + r0);
            a0 = fmaf(w, x.x, a0); a1 = fmaf(w, x.y, a1);
            a2 = fmaf(w, x.z, a2); a3 = fmaf(w, x.w, a3);
        }
        s_comb[(HDIM + h) * PAD + r0 + 0] = fmaxf(a0, 0.f);
        s_comb[(HDIM + h) * PAD + r0 + 1] = fmaxf(a1, 0.f);
        s_comb[(HDIM + h) * PAD + r0 + 2] = fmaxf(a2, 0.f);
        s_comb[(HDIM + h) * PAD + r0 + 3] = fmaxf(a3, 0.f);
    }
    __syncthreads();

    // ---- stage 5: a1 = relu(combined@wa1_w+b) ----
    {
        float ba = wa1_b[h];
        float a0 = ba, a1v = ba, a2 = ba, a3 = ba;
        #pragma unroll 4
        for (int k = 0; k < 2 * HDIM; k++) {
            float w  = wa1_w[k * HDIM + h];
            float4 x = *(const float4*)(s_comb + k * PAD + r0);
            a0  = fmaf(w, x.x, a0);  a1v = fmaf(w, x.y, a1v);
            a2  = fmaf(w, x.z, a2);  a3  = fmaf(w, x.w, a3);
        }
        s_a1[h * PAD + r0 + 0] = fmaxf(a0,  0.f);
        s_a1[h * PAD + r0 + 1] = fmaxf(a1v, 0.f);
        s_a1[h * PAD + r0 + 2] = fmaxf(a2,  0.f);
        s_a1[h * PAD + r0 + 3] = fmaxf(a3,  0.f);
    }
    __syncthreads();

    // ---- stage 6: logits = a1 @ wa2 + b  (each thread owns a column f, all 16 rows) ----
    for (int f = tid; f < NF; f += THREADS) {
        float acc[TB];
        float bb = wa2_b[f];
        #pragma unroll
        for (int r = 0; r < TB; r++) acc[r] = bb;
        #pragma unroll 4
        for (int k = 0; k < HDIM; k++) {
            float w = wa2_w[k * NF + f];
            #pragma unroll
            for (int q4 = 0; q4 < 4; q4++) {
                float4 x = *(const float4*)(s_a1 + k * PAD + q4 * 4);
                acc[q4 * 4 + 0] = fmaf(w, x.x, acc[q4 * 4 + 0]);
                acc[q4 * 4 + 1] = fmaf(w, x.y, acc[q4 * 4 + 1]);
                acc[q4 * 4 + 2] = fmaf(w, x.z, acc[q4 * 4 + 2]);
                acc[q4 * 4 + 3] = fmaf(w, x.w, acc[q4 * 4 + 3]);
            }
        }
        #pragma unroll
        for (int r = 0; r < TB; r++) s_attn[r * NF + f] = acc[r];
    }
    __syncthreads();

    // ---- stage 7: softmax per row (warp per row), write attn to gmem ----
    for (int r = warp; r < TB; r += THREADS / 32) {
        float mx = -1e30f;
        for (int f = lane; f < NF; f += 32) mx = fmaxf(mx, s_attn[r * NF + f]);
        #pragma unroll
        for (int o = 16; o; o >>= 1) mx = fmaxf(mx, __shfl_xor_sync(0xffffffffu, mx, o));
        float sum = 0.f;
        for (int f = lane; f < NF; f += 32) {
            float e = __expf(s_attn[r * NF + f] - mx);
            s_attn[r * NF + f] = e;
            sum += e;
        }
        #pragma unroll
        for (int o = 16; o; o >>= 1) sum += __shfl_xor_sync(0xffffffffu, sum, o);
        float inv = 1.f / sum;
        for (int f = lane; f < NF; f += 32) {
            float a = s_attn[r * NF + f] * inv;
            s_attn[r * NF + f] = a;
            out_attn[(size_t)(row0 + r) * NF + f] = a;
        }
    }

    // ---- stage 8: shape functions (thread owns a function f, loops 16 rows, weights in regs) ----
    for (int f = tid; f < NF; f += THREADS) {
        if (f < N1) {
            int n = f;
            float w1[8], b1[8], w2[32], b2v[4], w3[4];
            #pragma unroll
            for (int j = 0; j < 8; j++) { w1[j] = fabsf(w1_1[n * 8 + j]); b1[j] = b1_1[n * 8 + j]; }
            #pragma unroll
            for (int j = 0; j < 32; j++) w2[j] = fabsf(w2_1[n * 32 + j]);
            #pragma unroll
            for (int j = 0; j < 4; j++) { b2v[j] = b2_1[n * 4 + j]; w3[j] = fabsf(w3_1[n * 4 + j]); }
            float b3v = b3_1[n];
            for (int r = 0; r < TB; r++) {
                float x = s_q[r * NAG + n];
                float h1[8];
                #pragma unroll
                for (int j = 0; j < 8; j++) h1[j] = elu_f(fmaf(x, w1[j], b1[j]));
                float outv = b3v;
                #pragma unroll
                for (int j = 0; j < 4; j++) {
                    float a = b2v[j];
                    #pragma unroll
                    for (int k = 0; k < 8; k++) a = fmaf(h1[k], w2[k * 4 + j], a);
                    outv = fmaf(elu_f(a), w3[j], outv);
                }
                s_shape[r * NF + f] = outv;
                out_shape[(size_t)(row0 + r) * NF + f] = outv;
            }
        } else {
            int p = f - N1;
            int ii = 0, rem = p, cnt = NAG - 1;
            while (rem >= cnt) { rem -= cnt; cnt--; ii++; }
            int jj = ii + 1 + rem;
            float w1[16], b1[8], w2[32], b2v[4], w3[4];
            #pragma unroll
            for (int j = 0; j < 16; j++) w1[j] = fabsf(w1_2[p * 16 + j]);
            #pragma unroll
            for (int j = 0; j < 8; j++)  b1[j] = b1_2[p * 8 + j];
            #pragma unroll
            for (int j = 0; j < 32; j++) w2[j] = fabsf(w2_2[p * 32 + j]);
            #pragma unroll
            for (int j = 0; j < 4; j++) { b2v[j] = b2_2[p * 4 + j]; w3[j] = fabsf(w3_2[p * 4 + j]); }
            float b3v = b3_2[p];
            for (int r = 0; r < TB; r++) {
                float xi = s_q[r * NAG + ii];
                float xj = s_q[r * NAG + jj];
                float h1[8];
                #pragma unroll
                for (int j = 0; j < 8; j++)
                    h1[j] = elu_f(fmaf(xj, w1[8 + j], fmaf(xi, w1[j], b1[j])));
                float outv = b3v;
                #pragma unroll
                for (int j = 0; j < 4; j++) {
                    float a = b2v[j];
                    #pragma unroll
                    for (int k = 0; k < 8; k++) a = fmaf(h1[k], w2[k * 4 + j], a);
                    outv = fmaf(elu_f(a), w3[j], outv);
                }
                s_shape[r * NF + f] = outv;
                out_shape[(size_t)(row0 + r) * NF + f] = outv;
            }
        }
    }
    __syncthreads();

    // ---- stage 9: weighted sum + bias -> q_total ----
    for (int r = warp; r < TB; r += THREADS / 32) {
        float acc = 0.f;
        for (int f = lane; f < NF; f += 32)
            acc = fmaf(s_attn[r * NF + f], s_shape[r * NF + f], acc);
        #pragma unroll
        for (int o = 16; o; o >>= 1) acc += __shfl_xor_sync(0xffffffffu, acc, o);
        if (lane == 0) out_q[row0 + r] = acc + s_bias[r];
    }
}

extern "C" void kernel_launch(void* const* d_in, const int* in_sizes, int n_in,
                              void* d_out, int out_size)
{
    const float* A[27];
    for (int i = 0; i < 27; i++) A[i] = (const float*)d_in[i];
    int Btot = in_sizes[0] / NAG;   // agent_q_values is [B, 32]

    float* out       = (float*)d_out;
    float* out_q     = out;
    float* out_attn  = out + Btot;
    float* out_shape = out + Btot + (size_t)Btot * NF;

    size_t smem = (size_t)(SDIM * PAD + 2 * HDIM * PAD + HDIM * PAD
                           + 2 * TB * NF + TB * NAG + TB) * sizeof(float);
    cudaFuncSetAttribute(na2q_kernel, cudaFuncAttributeMaxDynamicSharedMemorySize, (int)smem);

    na2q_kernel<<<Btot / TB, THREADS, smem>>>(
        A[0], A[1], A[2],
        A[3], A[4], A[5], A[6], A[7], A[8],
        A[9], A[10], A[11], A[12], A[13], A[14],
        A[15], A[16], A[17], A[18],
        A[19], A[20], A[21], A[22],
        A[23], A[24], A[25], A[26],
        out_q, out_attn, out_shape);
}

// round 4
// speedup vs baseline: 2.0014x; 2.0014x over previous
#include <cuda_runtime.h>

#define TB      16
#define THREADS 256
#define NAG     32
#define SDIM    512
#define HDIM    64
#define N1      32
#define N2      496
#define NF      528
#define CHUNK   128
#define PBUF    36   // dup chunk buffer row stride (floats), 16B-aligned rows
#define PCMB    34   // dup combined buffer row stride (floats), 8B-aligned
#define PA1     20   // plain a1 row stride

typedef unsigned long long ull;

__device__ __forceinline__ ull fma2(ull a, ull b, ull c) {
    ull d; asm("fma.rn.f32x2 %0,%1,%2,%3;" : "=l"(d) : "l"(a), "l"(b), "l"(c)); return d;
}
__device__ __forceinline__ ull pack2(float lo, float hi) {
    ull r; asm("mov.b64 %0,{%1,%2};" : "=l"(r) : "f"(lo), "f"(hi)); return r;
}
__device__ __forceinline__ void unpack2(ull v, float& lo, float& hi) {
    asm("mov.b64 {%0,%1},%2;" : "=f"(lo), "=f"(hi) : "l"(v));
}
__device__ __forceinline__ float elu_f(float x) {
    return x > 0.f ? x : (__expf(x) - 1.f);
}

__global__ __launch_bounds__(THREADS, 3) void na2q_kernel(
    const float* __restrict__ q_in,   const float* __restrict__ state,  const float* __restrict__ sem,
    const float* __restrict__ w1_1,   const float* __restrict__ b1_1,
    const float* __restrict__ w2_1,   const float* __restrict__ b2_1,
    const float* __restrict__ w3_1,   const float* __restrict__ b3_1,
    const float* __restrict__ w1_2,   const float* __restrict__ b1_2,
    const float* __restrict__ w2_2,   const float* __restrict__ b2_2,
    const float* __restrict__ w3_2,   const float* __restrict__ b3_2,
    const float* __restrict__ ws_w,   const float* __restrict__ ws_b,
    const float* __restrict__ wz_w,   const float* __restrict__ wz_b,
    const float* __restrict__ wa1_w,  const float* __restrict__ wa1_b,
    const float* __restrict__ wa2_w,  const float* __restrict__ wa2_b,
    const float* __restrict__ wb1_w,  const float* __restrict__ wb1_b,
    const float* __restrict__ wb2_w,  const float* __restrict__ wb2_b,
    float* __restrict__ out_q, float* __restrict__ out_attn, float* __restrict__ out_shape)
{
    extern __shared__ float smf[];
    // layout (floats): [s_attn 8448 | s_comb 128*34 | s_a1 64*20 | s_q 512 | s_bias 16]
    float* s_attn = smf;                     // aliased: s_buf (128*36=4608) lives here too
    float* s_buf  = smf;
    float* s_comb = smf + TB * NF;           // 8448
    float* s_a1   = s_comb + 128 * PCMB;     // +4352
    float* s_q    = s_a1 + HDIM * PA1;       // +1280
    float* s_bias = s_q + TB * NAG;          // +512

    const int tid  = threadIdx.x;
    const int row0 = blockIdx.x * TB;
    const int hp   = tid & 31;      // column pair index (cols 2hp, 2hp+1)
    const int rg   = tid >> 5;      // row-group (rows 2rg, 2rg+1); == warp id
    const int h0   = 2 * hp;
    const int r0v  = 2 * rg;
    const int r1v  = r0v + 1;
    const int warp = tid >> 5;
    const int lane = tid & 31;

    // ---- load q tile ----
    for (int i = tid; i < TB * NAG; i += THREADS) s_q[i] = q_in[row0 * NAG + i];

    // ================= stage B: state enc + bias net (two fused GEMVs) =================
    ull aS0 = pack2(ws_b[h0],  ws_b[h0 + 1]);   ull aS1 = aS0;
    ull aB0 = pack2(wb1_b[h0], wb1_b[h0 + 1]);  ull aB1 = aB0;
    for (int c = 0; c < SDIM / CHUNK; c++) {
        __syncthreads();
        for (int i = tid; i < TB * CHUNK; i += THREADS) {
            int r = i >> 7, k = i & (CHUNK - 1);
            float v = state[(row0 + r) * SDIM + c * CHUNK + k];
            *(float2*)(s_buf + k * PBUF + 2 * r) = make_float2(v, v);
        }
        __syncthreads();
        const float* wSp = ws_w  + c * CHUNK * HDIM + h0;
        const float* wBp = wb1_w + c * CHUNK * HDIM + h0;
        #pragma unroll 4
        for (int k = 0; k < CHUNK; k++) {
            ull wS = *(const ull*)(wSp + k * HDIM);
            ull wB = *(const ull*)(wBp + k * HDIM);
            ulonglong2 x = *(const ulonglong2*)(s_buf + k * PBUF + 4 * rg);
            aS0 = fma2(wS, x.x, aS0);  aS1 = fma2(wS, x.y, aS1);
            aB0 = fma2(wB, x.x, aB0);  aB1 = fma2(wB, x.y, aB1);
        }
    }
    {
        float v00, v01, v10, v11;
        unpack2(aS0, v00, v01);  // row r0: cols h0, h0+1
        unpack2(aS1, v10, v11);  // row r1
        float a;
        a = fmaxf(v00, 0.f); *(float2*)(s_comb + h0 * PCMB + 2 * r0v)       = make_float2(a, a);
        a = fmaxf(v10, 0.f); *(float2*)(s_comb + h0 * PCMB + 2 * r1v)       = make_float2(a, a);
        a = fmaxf(v01, 0.f); *(float2*)(s_comb + (h0 + 1) * PCMB + 2 * r0v) = make_float2(a, a);
        a = fmaxf(v11, 0.f); *(float2*)(s_comb + (h0 + 1) * PCMB + 2 * r1v) = make_float2(a, a);
        float b00, b01, b10, b11;
        unpack2(aB0, b00, b01);
        unpack2(aB1, b10, b11);
        float w2c0 = wb2_w[h0], w2c1 = wb2_w[h0 + 1];
        float c0 = fmaxf(b00, 0.f) * w2c0 + fmaxf(b01, 0.f) * w2c1;
        float c1 = fmaxf(b10, 0.f) * w2c0 + fmaxf(b11, 0.f) * w2c1;
        #pragma unroll
        for (int o = 16; o; o >>= 1) {
            c0 += __shfl_xor_sync(0xffffffffu, c0, o);
            c1 += __shfl_xor_sync(0xffffffffu, c1, o);
        }
        if (lane == 0) {
            float b3 = wb2_b[0];
            s_bias[r0v] = c0 + b3;
            s_bias[r1v] = c1 + b3;
        }
    }

    // ================= stage C: semantic encoder =================
    ull aZ0 = pack2(wz_b[h0], wz_b[h0 + 1]);  ull aZ1 = aZ0;
    for (int c = 0; c < SDIM / CHUNK; c++) {
        __syncthreads();
        for (int i = tid; i < TB * CHUNK; i += THREADS) {
            int r = i >> 7, k = i & (CHUNK - 1);
            float v = sem[(row0 + r) * SDIM + c * CHUNK + k];
            *(float2*)(s_buf + k * PBUF + 2 * r) = make_float2(v, v);
        }
        __syncthreads();
        const float* wZp = wz_w + c * CHUNK * HDIM + h0;
        #pragma unroll 4
        for (int k = 0; k < CHUNK; k++) {
            ull wZ = *(const ull*)(wZp + k * HDIM);
            ulonglong2 x = *(const ulonglong2*)(s_buf + k * PBUF + 4 * rg);
            aZ0 = fma2(wZ, x.x, aZ0);  aZ1 = fma2(wZ, x.y, aZ1);
        }
    }
    {
        float v00, v01, v10, v11, a;
        unpack2(aZ0, v00, v01);
        unpack2(aZ1, v10, v11);
        int cb = (HDIM + h0) * PCMB;
        a = fmaxf(v00, 0.f); *(float2*)(s_comb + cb + 2 * r0v)        = make_float2(a, a);
        a = fmaxf(v10, 0.f); *(float2*)(s_comb + cb + 2 * r1v)        = make_float2(a, a);
        a = fmaxf(v01, 0.f); *(float2*)(s_comb + cb + PCMB + 2 * r0v) = make_float2(a, a);
        a = fmaxf(v11, 0.f); *(float2*)(s_comb + cb + PCMB + 2 * r1v) = make_float2(a, a);
    }
    __syncthreads();

    // ================= stage D: a1 = relu(combined @ wa1 + b) =================
    {
        ull a0 = pack2(wa1_b[h0], wa1_b[h0 + 1]);  ull a1p = a0;
        #pragma unroll 4
        for (int k = 0; k < 2 * HDIM; k++) {
            ull w  = *(const ull*)(wa1_w + k * HDIM + h0);
            ull x0 = *(const ull*)(s_comb + k * PCMB + 4 * rg);
            ull x1 = *(const ull*)(s_comb + k * PCMB + 4 * rg + 2);
            a0  = fma2(w, x0, a0);
            a1p = fma2(w, x1, a1p);
        }
        float v00, v01, v10, v11;
        unpack2(a0,  v00, v01);
        unpack2(a1p, v10, v11);
        s_a1[h0 * PA1 + r0v]       = fmaxf(v00, 0.f);
        s_a1[h0 * PA1 + r1v]       = fmaxf(v10, 0.f);
        s_a1[(h0 + 1) * PA1 + r0v] = fmaxf(v01, 0.f);
        s_a1[(h0 + 1) * PA1 + r1v] = fmaxf(v11, 0.f);
    }
    __syncthreads();

    // ================= stage E: logits = a1 @ wa2 + b  (writes s_attn, aliases s_buf) =================
    for (int f = tid; f < NF; f += THREADS) {
        float bb = wa2_b[f];
        ull acc[8];
        ull bb2 = pack2(bb, bb);
        #pragma unroll
        for (int i = 0; i < 8; i++) acc[i] = bb2;
        #pragma unroll 4
        for (int k = 0; k < HDIM; k++) {
            float w = wa2_w[k * NF + f];
            ull ww = pack2(w, w);
            const ulonglong2* xp = (const ulonglong2*)(s_a1 + k * PA1);
            ulonglong2 xa = xp[0], xb = xp[1], xc = xp[2], xd = xp[3];
            acc[0] = fma2(ww, xa.x, acc[0]);  acc[1] = fma2(ww, xa.y, acc[1]);
            acc[2] = fma2(ww, xb.x, acc[2]);  acc[3] = fma2(ww, xb.y, acc[3]);
            acc[4] = fma2(ww, xc.x, acc[4]);  acc[5] = fma2(ww, xc.y, acc[5]);
            acc[6] = fma2(ww, xd.x, acc[6]);  acc[7] = fma2(ww, xd.y, acc[7]);
        }
        #pragma unroll
        for (int i = 0; i < 8; i++) {
            float lo, hi;
            unpack2(acc[i], lo, hi);
            s_attn[(2 * i) * NF + f]     = lo;
            s_attn[(2 * i + 1) * NF + f] = hi;
        }
    }
    __syncthreads();

    // ================= stage F: softmax per row =================
    for (int r = warp; r < TB; r += THREADS / 32) {
        float mx = -1e30f;
        for (int f = lane; f < NF; f += 32) mx = fmaxf(mx, s_attn[r * NF + f]);
        #pragma unroll
        for (int o = 16; o; o >>= 1) mx = fmaxf(mx, __shfl_xor_sync(0xffffffffu, mx, o));
        float sum = 0.f;
        for (int f = lane; f < NF; f += 32) {
            float e = __expf(s_attn[r * NF + f] - mx);
            s_attn[r * NF + f] = e;
            sum += e;
        }
        #pragma unroll
        for (int o = 16; o; o >>= 1) sum += __shfl_xor_sync(0xffffffffu, sum, o);
        float inv = 1.f / sum;
        for (int f = lane; f < NF; f += 32) {
            float a = s_attn[r * NF + f] * inv;
            s_attn[r * NF + f] = a;
            out_attn[(size_t)(row0 + r) * NF + f] = a;
        }
    }
    __syncthreads();

    // ================= stage G: shape fns; overwrite s_attn with attn*shape =================
    for (int f = tid; f < NF; f += THREADS) {
        if (f < N1) {
            int n = f;
            float w1[8], b1[8], w2[32], b2v[4], w3[4];
            #pragma unroll
            for (int j = 0; j < 8; j++) { w1[j] = fabsf(w1_1[n * 8 + j]); b1[j] = b1_1[n * 8 + j]; }
            #pragma unroll
            for (int j = 0; j < 32; j++) w2[j] = fabsf(w2_1[n * 32 + j]);
            #pragma unroll
            for (int j = 0; j < 4; j++) { b2v[j] = b2_1[n * 4 + j]; w3[j] = fabsf(w3_1[n * 4 + j]); }
            float b3v = b3_1[n];
            for (int r = 0; r < TB; r++) {
                float x = s_q[r * NAG + n];
                float h1[8];
                #pragma unroll
                for (int j = 0; j < 8; j++) h1[j] = elu_f(fmaf(x, w1[j], b1[j]));
                float outv = b3v;
                #pragma unroll
                for (int j = 0; j < 4; j++) {
                    float a = b2v[j];
                    #pragma unroll
                    for (int k = 0; k < 8; k++) a = fmaf(h1[k], w2[k * 4 + j], a);
                    outv = fmaf(elu_f(a), w3[j], outv);
                }
                out_shape[(size_t)(row0 + r) * NF + f] = outv;
                s_attn[r * NF + f] *= outv;
            }
        } else {
            int p = f - N1;
            int ii = 0, rem = p, cnt = NAG - 1;
            while (rem >= cnt) { rem -= cnt; cnt--; ii++; }
            int jj = ii + 1 + rem;
            float w1[16], b1[8], w2[32], b2v[4], w3[4];
            #pragma unroll
            for (int j = 0; j < 16; j++) w1[j] = fabsf(w1_2[p * 16 + j]);
            #pragma unroll
            for (int j = 0; j < 8; j++)  b1[j] = b1_2[p * 8 + j];
            #pragma unroll
            for (int j = 0; j < 32; j++) w2[j] = fabsf(w2_2[p * 32 + j]);
            #pragma unroll
            for (int j = 0; j < 4; j++) { b2v[j] = b2_2[p * 4 + j]; w3[j] = fabsf(w3_2[p * 4 + j]); }
            float b3v = b3_2[p];
            for (int r = 0; r < TB; r++) {
                float xi = s_q[r * NAG + ii];
                float xj = s_q[r * NAG + jj];
                float h1[8];
                #pragma unroll
                for (int j = 0; j < 8; j++)
                    h1[j] = elu_f(fmaf(xj, w1[8 + j], fmaf(xi, w1[j], b1[j])));
                float outv = b3v;
                #pragma unroll
                for (int j = 0; j < 4; j++) {
                    float a = b2v[j];
                    #pragma unroll
                    for (int k = 0; k < 8; k++) a = fmaf(h1[k], w2[k * 4 + j], a);
                    outv = fmaf(elu_f(a), w3[j], outv);
                }
                out_shape[(size_t)(row0 + r) * NF + f] = outv;
                s_attn[r * NF + f] *= outv;
            }
        }
    }
    __syncthreads();

    // ================= stage H: q_total = sum(attn*shape) + bias =================
    for (int r = warp; r < TB; r += THREADS / 32) {
        float acc = 0.f;
        for (int f = lane; f < NF; f += 32) acc += s_attn[r * NF + f];
        #pragma unroll
        for (int o = 16; o; o >>= 1) acc += __shfl_xor_sync(0xffffffffu, acc, o);
        if (lane == 0) out_q[row0 + r] = acc + s_bias[r];
    }
}

extern "C" void kernel_launch(void* const* d_in, const int* in_sizes, int n_in,
                              void* d_out, int out_size)
{
    const float* A[27];
    for (int i = 0; i < 27; i++) A[i] = (const float*)d_in[i];
    int Btot = in_sizes[0] / NAG;

    float* out       = (float*)d_out;
    float* out_q     = out;
    float* out_attn  = out + Btot;
    float* out_shape = out + Btot + (size_t)Btot * NF;

    size_t smem = (size_t)(TB * NF + 128 * PCMB + HDIM * PA1 + TB * NAG + TB) * sizeof(float);
    cudaFuncSetAttribute(na2q_kernel, cudaFuncAttributeMaxDynamicSharedMemorySize, (int)smem);

    na2q_kernel<<<Btot / TB, THREADS, smem>>>(
        A[0], A[1], A[2],
        A[3], A[4], A[5], A[6], A[7], A[8],
        A[9], A[10], A[11], A[12], A[13], A[14],
        A[15], A[16], A[17], A[18],
        A[19], A[20], A[21], A[22],
        A[23], A[24], A[25], A[26],
        out_q, out_attn, out_shape);
}

// round 5
// speedup vs baseline: 2.3858x; 1.1921x over previous
#include <cuda_runtime.h>

#define TB      16
#define THREADS 256
#define NAG     32
#define SDIM    512
#define HDIM    64
#define N1      32
#define N2      496
#define NF      528
#define CHUNK   128
#define PBUF    36   // dup chunk tile row stride (floats): 32 used + 4 pad, 16B-aligned rows
#define PCMB    34   // dup combined buffer row stride
#define PA1     20   // plain a1 row stride

typedef unsigned long long ull;

__device__ __forceinline__ ull fma2(ull a, ull b, ull c) {
    ull d; asm("fma.rn.f32x2 %0,%1,%2,%3;" : "=l"(d) : "l"(a), "l"(b), "l"(c)); return d;
}
__device__ __forceinline__ ull pack2(float lo, float hi) {
    ull r; asm("mov.b64 %0,{%1,%2};" : "=l"(r) : "f"(lo), "f"(hi)); return r;
}
__device__ __forceinline__ void unpack2(ull v, float& lo, float& hi) {
    asm("mov.b64 {%0,%1},%2;" : "=f"(lo), "=f"(hi) : "l"(v));
}
__device__ __forceinline__ float elu_f(float x) {
    return x > 0.f ? x : (__expf(x) - 1.f);
}

__global__ __launch_bounds__(THREADS, 3) void na2q_kernel(
    const float* __restrict__ q_in,   const float* __restrict__ state,  const float* __restrict__ sem,
    const float* __restrict__ w1_1,   const float* __restrict__ b1_1,
    const float* __restrict__ w2_1,   const float* __restrict__ b2_1,
    const float* __restrict__ w3_1,   const float* __restrict__ b3_1,
    const float* __restrict__ w1_2,   const float* __restrict__ b1_2,
    const float* __restrict__ w2_2,   const float* __restrict__ b2_2,
    const float* __restrict__ w3_2,   const float* __restrict__ b3_2,
    const float* __restrict__ ws_w,   const float* __restrict__ ws_b,
    const float* __restrict__ wz_w,   const float* __restrict__ wz_b,
    const float* __restrict__ wa1_w,  const float* __restrict__ wa1_b,
    const float* __restrict__ wa2_w,  const float* __restrict__ wa2_b,
    const float* __restrict__ wb1_w,  const float* __restrict__ wb1_b,
    const float* __restrict__ wb2_w,  const float* __restrict__ wb2_b,
    float* __restrict__ out_q, float* __restrict__ out_attn, float* __restrict__ out_shape)
{
    extern __shared__ float smf[];
    // layout (floats):
    //   [0, 9216):      s_st (128*36) + s_se (128*36)   -- chunk tiles, ALIASED with s_attn
    //   [0, 8448):      s_attn (TB*NF)                   -- used after tiles are dead
    //   [9216, +4352):  s_comb (128*34, dup)
    //   then s_a1 (64*20), s_q (512), s_bias (16)
    float* s_attn = smf;
    float* s_st   = smf;
    float* s_se   = smf + CHUNK * PBUF;          // 4608
    float* s_comb = smf + 2 * CHUNK * PBUF;      // 9216
    float* s_a1   = s_comb + 2 * HDIM * PCMB;    // +4352
    float* s_q    = s_a1 + HDIM * PA1;           // +1280
    float* s_bias = s_q + TB * NAG;              // +512

    const int tid  = threadIdx.x;
    const int row0 = blockIdx.x * TB;
    const int warp = tid >> 5;
    const int lane = tid & 31;
    const int c0   = 2 * lane;          // this thread's column pair in the 64-wide encoders
    const int wgrp = warp & 3;          // row group (4 rows each)
    const int rbase = 4 * wgrp;
    const bool is_sem = (warp >= 4);

    // ---- load q tile ----
    for (int i = tid; i < TB * NAG; i += THREADS) s_q[i] = q_in[row0 * NAG + i];

    // ================= fused stage B+C: all three 512-dim encoders =================
    // warps 0-3: state -> [state_enc | bias_hidden], 4 rows each, both matrices
    // warps 4-7: sem   -> sem_enc, 4 rows each
    ull acc0[4], acc1[4];
    {
        float b0 = is_sem ? wz_b[c0]     : ws_b[c0];
        float b1 = is_sem ? wz_b[c0 + 1] : ws_b[c0 + 1];
        ull bi = pack2(b0, b1);
        ull bB = is_sem ? 0ull : pack2(wb1_b[c0], wb1_b[c0 + 1]);
        #pragma unroll
        for (int j = 0; j < 4; j++) { acc0[j] = bi; acc1[j] = bB; }
    }
    const float* w0base = is_sem ? wz_w : ws_w;

    for (int c = 0; c < SDIM / CHUNK; c++) {
        __syncthreads();
        // stage both tiles (dup layout [k][2r], stride 36)
        for (int i = tid; i < TB * CHUNK; i += THREADS) {
            int r = i >> 7, k = i & (CHUNK - 1);
            float v = state[(row0 + r) * SDIM + c * CHUNK + k];
            *(float2*)(s_st + k * PBUF + 2 * r) = make_float2(v, v);
        }
        for (int i = tid; i < TB * CHUNK; i += THREADS) {
            int r = i >> 7, k = i & (CHUNK - 1);
            float v = sem[(row0 + r) * SDIM + c * CHUNK + k];
            *(float2*)(s_se + k * PBUF + 2 * r) = make_float2(v, v);
        }
        __syncthreads();

        if (!is_sem) {
            const float* wp0 = ws_w  + (c * CHUNK) * HDIM + c0;
            const float* wp1 = wb1_w + (c * CHUNK) * HDIM + c0;
            #pragma unroll 8
            for (int k = 0; k < CHUNK; k++) {
                ull w0 = *(const ull*)(wp0 + k * HDIM);
                ull w1 = *(const ull*)(wp1 + k * HDIM);
                ulonglong2 xA = *(const ulonglong2*)(s_st + k * PBUF + 2 * rbase);
                ulonglong2 xB = *(const ulonglong2*)(s_st + k * PBUF + 2 * rbase + 4);
                acc0[0] = fma2(w0, xA.x, acc0[0]);  acc0[1] = fma2(w0, xA.y, acc0[1]);
                acc0[2] = fma2(w0, xB.x, acc0[2]);  acc0[3] = fma2(w0, xB.y, acc0[3]);
                acc1[0] = fma2(w1, xA.x, acc1[0]);  acc1[1] = fma2(w1, xA.y, acc1[1]);
                acc1[2] = fma2(w1, xB.x, acc1[2]);  acc1[3] = fma2(w1, xB.y, acc1[3]);
            }
        } else {
            const float* wp0 = wz_w + (c * CHUNK) * HDIM + c0;
            #pragma unroll 8
            for (int k = 0; k < CHUNK; k++) {
                ull w0 = *(const ull*)(wp0 + k * HDIM);
                ulonglong2 xA = *(const ulonglong2*)(s_se + k * PBUF + 2 * rbase);
                ulonglong2 xB = *(const ulonglong2*)(s_se + k * PBUF + 2 * rbase + 4);
                acc0[0] = fma2(w0, xA.x, acc0[0]);  acc0[1] = fma2(w0, xA.y, acc0[1]);
                acc0[2] = fma2(w0, xB.x, acc0[2]);  acc0[3] = fma2(w0, xB.y, acc0[3]);
            }
        }
    }
    // epilogue: write encoder outputs (dup) / reduce bias net
    if (!is_sem) {
        float part[4];
        float w2c0 = wb2_w[c0], w2c1 = wb2_w[c0 + 1];
        #pragma unroll
        for (int j = 0; j < 4; j++) {
            int r = rbase + j;
            float v0, v1;
            unpack2(acc0[j], v0, v1);
            float a0 = fmaxf(v0, 0.f), a1 = fmaxf(v1, 0.f);
            *(float2*)(s_comb + c0 * PCMB + 2 * r)       = make_float2(a0, a0);
            *(float2*)(s_comb + (c0 + 1) * PCMB + 2 * r) = make_float2(a1, a1);
            float bv0, bv1;
            unpack2(acc1[j], bv0, bv1);
            part[j] = fmaxf(bv0, 0.f) * w2c0 + fmaxf(bv1, 0.f) * w2c1;
        }
        #pragma unroll
        for (int o = 16; o; o >>= 1) {
            #pragma unroll
            for (int j = 0; j < 4; j++) part[j] += __shfl_xor_sync(0xffffffffu, part[j], o);
        }
        if (lane == 0) {
            float b3 = wb2_b[0];
            #pragma unroll
            for (int j = 0; j < 4; j++) s_bias[rbase + j] = part[j] + b3;
        }
    } else {
        #pragma unroll
        for (int j = 0; j < 4; j++) {
            int r = rbase + j;
            float v0, v1;
            unpack2(acc0[j], v0, v1);
            float a0 = fmaxf(v0, 0.f), a1 = fmaxf(v1, 0.f);
            *(float2*)(s_comb + (HDIM + c0) * PCMB + 2 * r)     = make_float2(a0, a0);
            *(float2*)(s_comb + (HDIM + c0 + 1) * PCMB + 2 * r) = make_float2(a1, a1);
        }
    }
    __syncthreads();

    // ================= stage D: a1 = relu(combined @ wa1 + b) =================
    {
        const int rg = warp;           // row-pair owner (rows 2rg, 2rg+1)
        const int r0v = 2 * rg, r1v = r0v + 1;
        ull a0 = pack2(wa1_b[c0], wa1_b[c0 + 1]);  ull a1p = a0;
        #pragma unroll 8
        for (int k = 0; k < 2 * HDIM; k++) {
            ull w  = *(const ull*)(wa1_w + k * HDIM + c0);
            ull x0 = *(const ull*)(s_comb + k * PCMB + 4 * rg);
            ull x1 = *(const ull*)(s_comb + k * PCMB + 4 * rg + 2);
            a0  = fma2(w, x0, a0);
            a1p = fma2(w, x1, a1p);
        }
        float v00, v01, v10, v11;
        unpack2(a0,  v00, v01);
        unpack2(a1p, v10, v11);
        s_a1[c0 * PA1 + r0v]       = fmaxf(v00, 0.f);
        s_a1[c0 * PA1 + r1v]       = fmaxf(v10, 0.f);
        s_a1[(c0 + 1) * PA1 + r0v] = fmaxf(v01, 0.f);
        s_a1[(c0 + 1) * PA1 + r1v] = fmaxf(v11, 0.f);
    }
    __syncthreads();

    // ================= stage E: logits = a1 @ wa2 + b  (writes s_attn; tiles now dead) =================
    for (int f = tid; f < NF; f += THREADS) {
        float bb = wa2_b[f];
        ull acc[8];
        ull bb2 = pack2(bb, bb);
        #pragma unroll
        for (int i = 0; i < 8; i++) acc[i] = bb2;
        #pragma unroll 4
        for (int k = 0; k < HDIM; k++) {
            float w = wa2_w[k * NF + f];
            ull ww = pack2(w, w);
            const ulonglong2* xp = (const ulonglong2*)(s_a1 + k * PA1);
            ulonglong2 xa = xp[0], xb = xp[1], xc = xp[2], xd = xp[3];
            acc[0] = fma2(ww, xa.x, acc[0]);  acc[1] = fma2(ww, xa.y, acc[1]);
            acc[2] = fma2(ww, xb.x, acc[2]);  acc[3] = fma2(ww, xb.y, acc[3]);
            acc[4] = fma2(ww, xc.x, acc[4]);  acc[5] = fma2(ww, xc.y, acc[5]);
            acc[6] = fma2(ww, xd.x, acc[6]);  acc[7] = fma2(ww, xd.y, acc[7]);
        }
        #pragma unroll
        for (int i = 0; i < 8; i++) {
            float lo, hi;
            unpack2(acc[i], lo, hi);
            s_attn[(2 * i) * NF + f]     = lo;
            s_attn[(2 * i + 1) * NF + f] = hi;
        }
    }
    __syncthreads();

    // ================= stage F: softmax per row =================
    for (int r = warp; r < TB; r += THREADS / 32) {
        float mx = -1e30f;
        for (int f = lane; f < NF; f += 32) mx = fmaxf(mx, s_attn[r * NF + f]);
        #pragma unroll
        for (int o = 16; o; o >>= 1) mx = fmaxf(mx, __shfl_xor_sync(0xffffffffu, mx, o));
        float sum = 0.f;
        for (int f = lane; f < NF; f += 32) {
            float e = __expf(s_attn[r * NF + f] - mx);
            s_attn[r * NF + f] = e;
            sum += e;
        }
        #pragma unroll
        for (int o = 16; o; o >>= 1) sum += __shfl_xor_sync(0xffffffffu, sum, o);
        float inv = 1.f / sum;
        for (int f = lane; f < NF; f += 32) {
            float a = s_attn[r * NF + f] * inv;
            s_attn[r * NF + f] = a;
            out_attn[(size_t)(row0 + r) * NF + f] = a;
        }
    }
    __syncthreads();

    // ================= stage G: shape fns; overwrite s_attn with attn*shape =================
    for (int f = tid; f < NF; f += THREADS) {
        if (f < N1) {
            int n = f;
            float w1[8], b1[8], w2[32], b2v[4], w3[4];
            #pragma unroll
            for (int j = 0; j < 8; j++) { w1[j] = fabsf(w1_1[n * 8 + j]); b1[j] = b1_1[n * 8 + j]; }
            #pragma unroll
            for (int j = 0; j < 32; j++) w2[j] = fabsf(w2_1[n * 32 + j]);
            #pragma unroll
            for (int j = 0; j < 4; j++) { b2v[j] = b2_1[n * 4 + j]; w3[j] = fabsf(w3_1[n * 4 + j]); }
            float b3v = b3_1[n];
            for (int r = 0; r < TB; r++) {
                float x = s_q[r * NAG + n];
                float h1[8];
                #pragma unroll
                for (int j = 0; j < 8; j++) h1[j] = elu_f(fmaf(x, w1[j], b1[j]));
                float outv = b3v;
                #pragma unroll
                for (int j = 0; j < 4; j++) {
                    float a = b2v[j];
                    #pragma unroll
                    for (int k = 0; k < 8; k++) a = fmaf(h1[k], w2[k * 4 + j], a);
                    outv = fmaf(elu_f(a), w3[j], outv);
                }
                out_shape[(size_t)(row0 + r) * NF + f] = outv;
                s_attn[r * NF + f] *= outv;
            }
        } else {
            int p = f - N1;
            int ii = 0, rem = p, cnt = NAG - 1;
            while (rem >= cnt) { rem -= cnt; cnt--; ii++; }
            int jj = ii + 1 + rem;
            float w1[16], b1[8], w2[32], b2v[4], w3[4];
            #pragma unroll
            for (int j = 0; j < 16; j++) w1[j] = fabsf(w1_2[p * 16 + j]);
            #pragma unroll
            for (int j = 0; j < 8; j++)  b1[j] = b1_2[p * 8 + j];
            #pragma unroll
            for (int j = 0; j < 32; j++) w2[j] = fabsf(w2_2[p * 32 + j]);
            #pragma unroll
            for (int j = 0; j < 4; j++) { b2v[j] = b2_2[p * 4 + j]; w3[j] = fabsf(w3_2[p * 4 + j]); }
            float b3v = b3_2[p];
            for (int r = 0; r < TB; r++) {
                float xi = s_q[r * NAG + ii];
                float xj = s_q[r * NAG + jj];
                float h1[8];
                #pragma unroll
                for (int j = 0; j < 8; j++)
                    h1[j] = elu_f(fmaf(xj, w1[8 + j], fmaf(xi, w1[j], b1[j])));
                float outv = b3v;
                #pragma unroll
                for (int j = 0; j < 4; j++) {
                    float a = b2v[j];
                    #pragma unroll
                    for (int k = 0; k < 8; k++) a = fmaf(h1[k], w2[k * 4 + j], a);
                    outv = fmaf(elu_f(a), w3[j], outv);
                }
                out_shape[(size_t)(row0 + r) * NF + f] = outv;
                s_attn[r * NF + f] *= outv;
            }
        }
    }
    __syncthreads();

    // ================= stage H: q_total = sum(attn*shape) + bias =================
    for (int r = warp; r < TB; r += THREADS / 32) {
        float acc = 0.f;
        for (int f = lane; f < NF; f += 32) acc += s_attn[r * NF + f];
        #pragma unroll
        for (int o = 16; o; o >>= 1) acc += __shfl_xor_sync(0xffffffffu, acc, o);
        if (lane == 0) out_q[row0 + r] = acc + s_bias[r];
    }
}

extern "C" void kernel_launch(void* const* d_in, const int* in_sizes, int n_in,
                              void* d_out, int out_size)
{
    const float* A[27];
    for (int i = 0; i < 27; i++) A[i] = (const float*)d_in[i];
    int Btot = in_sizes[0] / NAG;

    float* out       = (float*)d_out;
    float* out_q     = out;
    float* out_attn  = out + Btot;
    float* out_shape = out + Btot + (size_t)Btot * NF;

    size_t smem = (size_t)(2 * CHUNK * PBUF + 2 * HDIM * PCMB + HDIM * PA1
                           + TB * NAG + TB) * sizeof(float);
    cudaFuncSetAttribute(na2q_kernel, cudaFuncAttributeMaxDynamicSharedMemorySize, (int)smem);

    na2q_kernel<<<Btot / TB, THREADS, smem>>>(
        A[0], A[1], A[2],
        A[3], A[4], A[5], A[6], A[7], A[8],
        A[9], A[10], A[11], A[12], A[13], A[14],
        A[15], A[16], A[17], A[18],
        A[19], A[20], A[21], A[22],
        A[23], A[24], A[25], A[26],
        out_q, out_attn, out_shape);
}

// round 6
// speedup vs baseline: 4.0337x; 1.6907x over previous
#include <cuda_runtime.h>
#include <cuda_bf16.h>
#include <cstdint>

#define TB      16
#define THREADS 256
#define NAG     32
#define SDIM    512
#define HDIM    64
#define N1      32
#define N2      496
#define NF      528

// ---------------- fragment table ----------------
#define NKS_ENC 32            // 512/16
#define NKS_D   8             // 128/16
#define NKS_E   4             // 64/16
#define NT_E    66            // 528/8
#define OFF_WS  0
#define OFF_WB  (8*NKS_ENC*32)               // 8192
#define OFF_WZ  (2*8*NKS_ENC*32)             // 16384
#define OFF_WA1 (3*8*NKS_ENC*32)             // 24576
#define OFF_WA2 (OFF_WA1 + 8*NKS_D*32)       // 26624
#define FRAG_TOTAL (OFF_WA2 + NT_E*NKS_E*32) // 35072

__device__ uint4 g_frag[FRAG_TOTAL];

// smem byte offsets (total 49216 B)
#define XS_H  0
#define XS_L  8448
#define XZ_H  16896
#define XZ_L  25344
#define CMB_H 33792
#define CMB_L 38144
#define A1_H  42496
#define A1_L  44800
#define QOFF  47104
#define BOFF  49152
#define SMEM_TOTAL 49216

__device__ __forceinline__ uint32_t pack_bf2(__nv_bfloat16 lo, __nv_bfloat16 hi) {
    __nv_bfloat162 p; p.x = lo; p.y = hi;
    return *reinterpret_cast<uint32_t*>(&p);
}
__device__ __forceinline__ void split1(float v, __nv_bfloat16& h, __nv_bfloat16& l) {
    h = __float2bfloat16(v);
    l = __float2bfloat16(v - __bfloat162float(h));
}
__device__ __forceinline__ void ldm4(uint32_t* r, uint32_t addr) {
    asm volatile("ldmatrix.sync.aligned.m8n8.x4.shared.b16 {%0,%1,%2,%3}, [%4];"
        : "=r"(r[0]), "=r"(r[1]), "=r"(r[2]), "=r"(r[3]) : "r"(addr));
}
__device__ __forceinline__ void mma16816(float* d, const uint32_t* a, uint32_t b0, uint32_t b1) {
    asm volatile("mma.sync.aligned.m16n8k16.row.col.f32.bf16.bf16.f32 "
        "{%0,%1,%2,%3},{%4,%5,%6,%7},{%8,%9},{%0,%1,%2,%3};"
        : "+f"(d[0]), "+f"(d[1]), "+f"(d[2]), "+f"(d[3])
        : "r"(a[0]), "r"(a[1]), "r"(a[2]), "r"(a[3]), "r"(b0), "r"(b1));
}
__device__ __forceinline__ float elu_f(float x) {
    return x > 0.f ? x : (__expf(x) - 1.f);
}

// ---------------- prep: pack weights into per-lane B fragments ----------------
__global__ void prep_kernel(const float* __restrict__ ws_w, const float* __restrict__ wb1_w,
                            const float* __restrict__ wz_w, const float* __restrict__ wa1_w,
                            const float* __restrict__ wa2_w)
{
    int id = blockIdx.x * blockDim.x + threadIdx.x;
    if (id >= FRAG_TOTAL) return;
    const float* W; int N; int t, s;
    int l = id & 31;
    if (id < OFF_WB)       { W = ws_w;  N = 64; int loc = id;           t = loc >> 10; s = (loc >> 5) & 31; }
    else if (id < OFF_WZ)  { W = wb1_w; N = 64; int loc = id - OFF_WB;  t = loc >> 10; s = (loc >> 5) & 31; }
    else if (id < OFF_WA1) { W = wz_w;  N = 64; int loc = id - OFF_WZ;  t = loc >> 10; s = (loc >> 5) & 31; }
    else if (id < OFF_WA2) { W = wa1_w; N = 64; int loc = id - OFF_WA1; t = loc >> 8;  s = (loc >> 5) & 7;  }
    else                   { W = wa2_w; N = NF; int loc = id - OFF_WA2; t = loc >> 7;  s = (loc >> 5) & 3;  }
    int n = t * 8 + (l >> 2);
    int k = s * 16 + (l & 3) * 2;
    float v00 = W[(size_t)k * N + n],       v01 = W[(size_t)(k + 1) * N + n];
    float v10 = W[(size_t)(k + 8) * N + n], v11 = W[(size_t)(k + 9) * N + n];
    __nv_bfloat16 h00, l00, h01, l01, h10, l10, h11, l11;
    split1(v00, h00, l00); split1(v01, h01, l01);
    split1(v10, h10, l10); split1(v11, h11, l11);
    g_frag[id] = make_uint4(pack_bf2(h00, h01), pack_bf2(h10, h11),
                            pack_bf2(l00, l01), pack_bf2(l10, l11));
}

// ---------------- main fused kernel ----------------
__global__ __launch_bounds__(THREADS, 3) void na2q_kernel(
    const float* __restrict__ q_in,   const float* __restrict__ state,  const float* __restrict__ sem,
    const float* __restrict__ w1_1,   const float* __restrict__ b1_1,
    const float* __restrict__ w2_1,   const float* __restrict__ b2_1,
    const float* __restrict__ w3_1,   const float* __restrict__ b3_1,
    const float* __restrict__ w1_2,   const float* __restrict__ b1_2,
    const float* __restrict__ w2_2,   const float* __restrict__ b2_2,
    const float* __restrict__ w3_2,   const float* __restrict__ b3_2,
    const float* __restrict__ ws_b,   const float* __restrict__ wz_b,
    const float* __restrict__ wa1_b,  const float* __restrict__ wa2_b,
    const float* __restrict__ wb1_b,  const float* __restrict__ wb2_w,
    const float* __restrict__ wb2_b,
    float* __restrict__ out_q, float* __restrict__ out_attn, float* __restrict__ out_shape)
{
    extern __shared__ char smem[];
    float* s_attn = (float*)smem;                 // [16][528] fp32, aliases x chunk buffers
    float* s_q    = (float*)(smem + QOFF);        // [16][32]
    float* s_bias = (float*)(smem + BOFF);        // [16]

    const int tid  = threadIdx.x;
    const int row0 = blockIdx.x * TB;
    const int warp = tid >> 5;
    const int lane = tid & 31;
    const int g    = lane >> 2;
    const int cp   = (lane & 3) * 2;

    // ldmatrix per-lane addressing
    const int grp  = lane >> 3;
    const int arow = (lane & 7) + ((grp & 1) << 3);
    const int akof = ((grp >> 1) << 3) * 2;  // byte offset of k-half
    const uint32_t sbase  = (uint32_t)__cvta_generic_to_shared(smem);
    const uint32_t aoff_x = arow * 528 + akof;
    const uint32_t aoff_c = arow * 272 + akof;
    const uint32_t aoff_a = arow * 144 + akof;

    // init q tile + bias accumulator
    for (int i = tid; i < TB * NAG; i += THREADS) s_q[i] = q_in[row0 * NAG + i];
    if (tid < TB) s_bias[tid] = wb2_b[0];

    // ===== encoders: state_enc / bias_hidden / sem_enc via 3-term bf16 mma =====
    float dws[4] = {0,0,0,0}, dwb[4] = {0,0,0,0}, dwz[4] = {0,0,0,0};
    for (int c = 0; c < 2; c++) {
        __syncthreads();
        // convert x chunk (k in [256c, 256c+256)) to bf16 hi/lo smem tiles
        for (int i = tid; i < 1024; i += THREADS) {
            int r = i >> 6, kq = i & 63;
            float4 v = *(const float4*)(state + (size_t)(row0 + r) * SDIM + c * 256 + kq * 4);
            __nv_bfloat16 h0,l0,h1,l1,h2,l2,h3,l3;
            split1(v.x,h0,l0); split1(v.y,h1,l1); split1(v.z,h2,l2); split1(v.w,h3,l3);
            *(uint2*)(smem + XS_H + r * 528 + kq * 8) = make_uint2(pack_bf2(h0,h1), pack_bf2(h2,h3));
            *(uint2*)(smem + XS_L + r * 528 + kq * 8) = make_uint2(pack_bf2(l0,l1), pack_bf2(l2,l3));
            v = *(const float4*)(sem + (size_t)(row0 + r) * SDIM + c * 256 + kq * 4);
            split1(v.x,h0,l0); split1(v.y,h1,l1); split1(v.z,h2,l2); split1(v.w,h3,l3);
            *(uint2*)(smem + XZ_H + r * 528 + kq * 8) = make_uint2(pack_bf2(h0,h1), pack_bf2(h2,h3));
            *(uint2*)(smem + XZ_L + r * 528 + kq * 8) = make_uint2(pack_bf2(l0,l1), pack_bf2(l2,l3));
        }
        __syncthreads();
        #pragma unroll 4
        for (int ks = 0; ks < 16; ks++) {
            int s = c * 16 + ks;
            uint32_t ah[4], al[4], zh[4], zl[4];
            ldm4(ah, sbase + XS_H + aoff_x + ks * 32);
            ldm4(al, sbase + XS_L + aoff_x + ks * 32);
            uint4 bws = g_frag[OFF_WS + (warp * NKS_ENC + s) * 32 + lane];
            uint4 bwb = g_frag[OFF_WB + (warp * NKS_ENC + s) * 32 + lane];
            mma16816(dws, ah, bws.x, bws.y);
            mma16816(dws, ah, bws.z, bws.w);
            mma16816(dws, al, bws.x, bws.y);
            mma16816(dwb, ah, bwb.x, bwb.y);
            mma16816(dwb, ah, bwb.z, bwb.w);
            mma16816(dwb, al, bwb.x, bwb.y);
            ldm4(zh, sbase + XZ_H + aoff_x + ks * 32);
            ldm4(zl, sbase + XZ_L + aoff_x + ks * 32);
            uint4 bwz = g_frag[OFF_WZ + (warp * NKS_ENC + s) * 32 + lane];
            mma16816(dwz, zh, bwz.x, bwz.y);
            mma16816(dwz, zh, bwz.z, bwz.w);
            mma16816(dwz, zl, bwz.x, bwz.y);
        }
    }
    // epilogue: comb (bf16 hi/lo, dup-free) + bias partials
    {
        int c0c = 8 * warp + cp;
        float v; __nv_bfloat16 h, l;
        v = fmaxf(dws[0] + ws_b[c0c],   0.f); split1(v,h,l);
        *(__nv_bfloat16*)(smem + CMB_H + g*272 + c0c*2) = h;       *(__nv_bfloat16*)(smem + CMB_L + g*272 + c0c*2) = l;
        v = fmaxf(dws[1] + ws_b[c0c+1], 0.f); split1(v,h,l);
        *(__nv_bfloat16*)(smem + CMB_H + g*272 + (c0c+1)*2) = h;   *(__nv_bfloat16*)(smem + CMB_L + g*272 + (c0c+1)*2) = l;
        v = fmaxf(dws[2] + ws_b[c0c],   0.f); split1(v,h,l);
        *(__nv_bfloat16*)(smem + CMB_H + (g+8)*272 + c0c*2) = h;   *(__nv_bfloat16*)(smem + CMB_L + (g+8)*272 + c0c*2) = l;
        v = fmaxf(dws[3] + ws_b[c0c+1], 0.f); split1(v,h,l);
        *(__nv_bfloat16*)(smem + CMB_H + (g+8)*272 + (c0c+1)*2) = h; *(__nv_bfloat16*)(smem + CMB_L + (g+8)*272 + (c0c+1)*2) = l;

        int zc = 64 + c0c;
        v = fmaxf(dwz[0] + wz_b[c0c],   0.f); split1(v,h,l);
        *(__nv_bfloat16*)(smem + CMB_H + g*272 + zc*2) = h;        *(__nv_bfloat16*)(smem + CMB_L + g*272 + zc*2) = l;
        v = fmaxf(dwz[1] + wz_b[c0c+1], 0.f); split1(v,h,l);
        *(__nv_bfloat16*)(smem + CMB_H + g*272 + (zc+1)*2) = h;    *(__nv_bfloat16*)(smem + CMB_L + g*272 + (zc+1)*2) = l;
        v = fmaxf(dwz[2] + wz_b[c0c],   0.f); split1(v,h,l);
        *(__nv_bfloat16*)(smem + CMB_H + (g+8)*272 + zc*2) = h;    *(__nv_bfloat16*)(smem + CMB_L + (g+8)*272 + zc*2) = l;
        v = fmaxf(dwz[3] + wz_b[c0c+1], 0.f); split1(v,h,l);
        *(__nv_bfloat16*)(smem + CMB_H + (g+8)*272 + (zc+1)*2) = h; *(__nv_bfloat16*)(smem + CMB_L + (g+8)*272 + (zc+1)*2) = l;

        float hb0 = fmaxf(dwb[0] + wb1_b[c0c],   0.f) * wb2_w[c0c];
        float hb1 = fmaxf(dwb[1] + wb1_b[c0c+1], 0.f) * wb2_w[c0c+1];
        float hb2 = fmaxf(dwb[2] + wb1_b[c0c],   0.f) * wb2_w[c0c];
        float hb3 = fmaxf(dwb[3] + wb1_b[c0c+1], 0.f) * wb2_w[c0c+1];
        float p0 = hb0 + hb1, p1 = hb2 + hb3;
        p0 += __shfl_xor_sync(0xffffffffu, p0, 1); p0 += __shfl_xor_sync(0xffffffffu, p0, 2);
        p1 += __shfl_xor_sync(0xffffffffu, p1, 1); p1 += __shfl_xor_sync(0xffffffffu, p1, 2);
        if ((lane & 3) == 0) { atomicAdd(&s_bias[g], p0); atomicAdd(&s_bias[g + 8], p1); }
    }
    __syncthreads();

    // ===== stage D: a1 = relu(comb @ wa1 + b), one n8-tile per warp =====
    {
        float da[4] = {0,0,0,0};
        #pragma unroll
        for (int s = 0; s < 8; s++) {
            uint32_t ch[4], cl[4];
            ldm4(ch, sbase + CMB_H + aoff_c + s * 32);
            ldm4(cl, sbase + CMB_L + aoff_c + s * 32);
            uint4 b = g_frag[OFF_WA1 + (warp * NKS_D + s) * 32 + lane];
            mma16816(da, ch, b.x, b.y);
            mma16816(da, ch, b.z, b.w);
            mma16816(da, cl, b.x, b.y);
        }
        int ca = 8 * warp + cp;
        float v; __nv_bfloat16 h, l;
        v = fmaxf(da[0] + wa1_b[ca],   0.f); split1(v,h,l);
        *(__nv_bfloat16*)(smem + A1_H + g*144 + ca*2) = h;        *(__nv_bfloat16*)(smem + A1_L + g*144 + ca*2) = l;
        v = fmaxf(da[1] + wa1_b[ca+1], 0.f); split1(v,h,l);
        *(__nv_bfloat16*)(smem + A1_H + g*144 + (ca+1)*2) = h;    *(__nv_bfloat16*)(smem + A1_L + g*144 + (ca+1)*2) = l;
        v = fmaxf(da[2] + wa1_b[ca],   0.f); split1(v,h,l);
        *(__nv_bfloat16*)(smem + A1_H + (g+8)*144 + ca*2) = h;    *(__nv_bfloat16*)(smem + A1_L + (g+8)*144 + ca*2) = l;
        v = fmaxf(da[3] + wa1_b[ca+1], 0.f); split1(v,h,l);
        *(__nv_bfloat16*)(smem + A1_H + (g+8)*144 + (ca+1)*2) = h; *(__nv_bfloat16*)(smem + A1_L + (g+8)*144 + (ca+1)*2) = l;
    }
    __syncthreads();

    // ===== stage E: logits = a1 @ wa2 + b =====
    {
        uint32_t eh[4][4], el[4][4];
        #pragma unroll
        for (int s = 0; s < 4; s++) {
            ldm4(eh[s], sbase + A1_H + aoff_a + s * 32);
            ldm4(el[s], sbase + A1_L + aoff_a + s * 32);
        }
        for (int t = warp; t < NT_E; t += 8) {
            float d[4] = {0,0,0,0};
            #pragma unroll
            for (int s = 0; s < 4; s++) {
                uint4 b = g_frag[OFF_WA2 + (t * NKS_E + s) * 32 + lane];
                mma16816(d, eh[s], b.x, b.y);
                mma16816(d, eh[s], b.z, b.w);
                mma16816(d, el[s], b.x, b.y);
            }
            int fc = 8 * t + cp;
            s_attn[g * NF + fc]           = d[0] + wa2_b[fc];
            s_attn[g * NF + fc + 1]       = d[1] + wa2_b[fc + 1];
            s_attn[(g + 8) * NF + fc]     = d[2] + wa2_b[fc];
            s_attn[(g + 8) * NF + fc + 1] = d[3] + wa2_b[fc + 1];
        }
    }
    __syncthreads();

    // ===== stage F: softmax per row =====
    for (int r = warp; r < TB; r += THREADS / 32) {
        float mx = -1e30f;
        for (int f = lane; f < NF; f += 32) mx = fmaxf(mx, s_attn[r * NF + f]);
        #pragma unroll
        for (int o = 16; o; o >>= 1) mx = fmaxf(mx, __shfl_xor_sync(0xffffffffu, mx, o));
        float sum = 0.f;
        for (int f = lane; f < NF; f += 32) {
            float e = __expf(s_attn[r * NF + f] - mx);
            s_attn[r * NF + f] = e;
            sum += e;
        }
        #pragma unroll
        for (int o = 16; o; o >>= 1) sum += __shfl_xor_sync(0xffffffffu, sum, o);
        float inv = 1.f / sum;
        for (int f = lane; f < NF; f += 32) {
            float a = s_attn[r * NF + f] * inv;
            s_attn[r * NF + f] = a;
            out_attn[(size_t)(row0 + r) * NF + f] = a;
        }
    }
    __syncthreads();

    // ===== stage G: shape fns; overwrite s_attn with attn*shape =====
    for (int f = tid; f < NF; f += THREADS) {
        if (f < N1) {
            int n = f;
            float w1[8], b1[8], w2[32], b2v[4], w3[4];
            #pragma unroll
            for (int j = 0; j < 8; j++) { w1[j] = fabsf(w1_1[n * 8 + j]); b1[j] = b1_1[n * 8 + j]; }
            #pragma unroll
            for (int j = 0; j < 32; j++) w2[j] = fabsf(w2_1[n * 32 + j]);
            #pragma unroll
            for (int j = 0; j < 4; j++) { b2v[j] = b2_1[n * 4 + j]; w3[j] = fabsf(w3_1[n * 4 + j]); }
            float b3v = b3_1[n];
            for (int r = 0; r < TB; r++) {
                float x = s_q[r * NAG + n];
                float h1[8];
                #pragma unroll
                for (int j = 0; j < 8; j++) h1[j] = elu_f(fmaf(x, w1[j], b1[j]));
                float outv = b3v;
                #pragma unroll
                for (int j = 0; j < 4; j++) {
                    float a = b2v[j];
                    #pragma unroll
                    for (int k = 0; k < 8; k++) a = fmaf(h1[k], w2[k * 4 + j], a);
                    outv = fmaf(elu_f(a), w3[j], outv);
                }
                out_shape[(size_t)(row0 + r) * NF + f] = outv;
                s_attn[r * NF + f] *= outv;
            }
        } else {
            int p = f - N1;
            int ii = 0, rem = p, cnt = NAG - 1;
            while (rem >= cnt) { rem -= cnt; cnt--; ii++; }
            int jj = ii + 1 + rem;
            float w1[16], b1[8], w2[32], b2v[4], w3[4];
            #pragma unroll
            for (int j = 0; j < 16; j++) w1[j] = fabsf(w1_2[p * 16 + j]);
            #pragma unroll
            for (int j = 0; j < 8; j++)  b1[j] = b1_2[p * 8 + j];
            #pragma unroll
            for (int j = 0; j < 32; j++) w2[j] = fabsf(w2_2[p * 32 + j]);
            #pragma unroll
            for (int j = 0; j < 4; j++) { b2v[j] = b2_2[p * 4 + j]; w3[j] = fabsf(w3_2[p * 4 + j]); }
            float b3v = b3_2[p];
            for (int r = 0; r < TB; r++) {
                float xi = s_q[r * NAG + ii];
                float xj = s_q[r * NAG + jj];
                float h1[8];
                #pragma unroll
                for (int j = 0; j < 8; j++)
                    h1[j] = elu_f(fmaf(xj, w1[8 + j], fmaf(xi, w1[j], b1[j])));
                float outv = b3v;
                #pragma unroll
                for (int j = 0; j < 4; j++) {
                    float a = b2v[j];
                    #pragma unroll
                    for (int k = 0; k < 8; k++) a = fmaf(h1[k], w2[k * 4 + j], a);
                    outv = fmaf(elu_f(a), w3[j], outv);
                }
                out_shape[(size_t)(row0 + r) * NF + f] = outv;
                s_attn[r * NF + f] *= outv;
            }
        }
    }
    __syncthreads();

    // ===== stage H: q_total =====
    for (int r = warp; r < TB; r += THREADS / 32) {
        float acc = 0.f;
        for (int f = lane; f < NF; f += 32) acc += s_attn[r * NF + f];
        #pragma unroll
        for (int o = 16; o; o >>= 1) acc += __shfl_xor_sync(0xffffffffu, acc, o);
        if (lane == 0) out_q[row0 + r] = acc + s_bias[r];
    }
}

extern "C" void kernel_launch(void* const* d_in, const int* in_sizes, int n_in,
                              void* d_out, int out_size)
{
    const float* A[27];
    for (int i = 0; i < 27; i++) A[i] = (const float*)d_in[i];
    int Btot = in_sizes[0] / NAG;

    float* out       = (float*)d_out;
    float* out_q     = out;
    float* out_attn  = out + Btot;
    float* out_shape = out + Btot + (size_t)Btot * NF;

    // input order: q, state, sem, [w1_1..b3_2]=3..14, ws_w=15, ws_b=16, wz_w=17, wz_b=18,
    // wa1_w=19, wa1_b=20, wa2_w=21, wa2_b=22, wb1_w=23, wb1_b=24, wb2_w=25, wb2_b=26
    prep_kernel<<<(FRAG_TOTAL + 255) / 256, 256>>>(A[15], A[23], A[17], A[19], A[21]);

    cudaFuncSetAttribute(na2q_kernel, cudaFuncAttributeMaxDynamicSharedMemorySize, SMEM_TOTAL);
    na2q_kernel<<<Btot / TB, THREADS, SMEM_TOTAL>>>(
        A[0], A[1], A[2],
        A[3], A[4], A[5], A[6], A[7], A[8],
        A[9], A[10], A[11], A[12], A[13], A[14],
        A[16], A[18],        // ws_b, wz_b
        A[20], A[22],        // wa1_b, wa2_b
        A[24], A[25], A[26], // wb1_b, wb2_w, wb2_b
        out_q, out_attn, out_shape);
}

// round 7
// speedup vs baseline: 5.8519x; 1.4508x over previous
#include <cuda_runtime.h>
#include <cuda_bf16.h>
#include <cstdint>

#define TB      16
#define THREADS 256
#define NAG     32
#define SDIM    512
#define HDIM    64
#define N1      32
#define N2      496
#define NF      528

// ---------------- fragment table ----------------
#define NKS_ENC 32            // 512/16
#define NKS_D   8             // 128/16
#define NKS_E   4             // 64/16
#define NT_E    66            // 528/8
#define OFF_WS  0
#define OFF_WB  (8*NKS_ENC*32)               // 8192
#define OFF_WZ  (2*8*NKS_ENC*32)             // 16384
#define OFF_WA1 (3*8*NKS_ENC*32)             // 24576
#define OFF_WA2 (OFF_WA1 + 8*NKS_D*32)       // 26624
#define FRAG_TOTAL (OFF_WA2 + NT_E*NKS_E*32) // 35072

__device__ uint4 g_frag[FRAG_TOTAL];

// transposed |w| shape-fn weights: component-major, fn minor (coalesced across lanes)
#define SH2_C 65
#define SH1_C 57
__device__ float g_sh2[SH2_C * N2];
__device__ float g_sh1[SH1_C * N1];
__device__ int2  g_pair[N2];

// smem byte offsets (total 49216 B)
#define XS_H  0
#define XS_L  8448
#define XZ_H  16896
#define XZ_L  25344
#define CMB_H 33792
#define CMB_L 38144
#define A1_H  42496
#define A1_L  44800
#define QOFF  47104
#define BOFF  49152
#define SMEM_TOTAL 49216

__device__ __forceinline__ uint32_t pack_bf2(__nv_bfloat16 lo, __nv_bfloat16 hi) {
    __nv_bfloat162 p; p.x = lo; p.y = hi;
    return *reinterpret_cast<uint32_t*>(&p);
}
__device__ __forceinline__ void split1(float v, __nv_bfloat16& h, __nv_bfloat16& l) {
    h = __float2bfloat16(v);
    l = __float2bfloat16(v - __bfloat162float(h));
}
__device__ __forceinline__ void ldm4(uint32_t* r, uint32_t addr) {
    asm volatile("ldmatrix.sync.aligned.m8n8.x4.shared.b16 {%0,%1,%2,%3}, [%4];"
        : "=r"(r[0]), "=r"(r[1]), "=r"(r[2]), "=r"(r[3]) : "r"(addr));
}
__device__ __forceinline__ void mma16816(float* d, const uint32_t* a, uint32_t b0, uint32_t b1) {
    asm volatile("mma.sync.aligned.m16n8k16.row.col.f32.bf16.bf16.f32 "
        "{%0,%1,%2,%3},{%4,%5,%6,%7},{%8,%9},{%0,%1,%2,%3};"
        : "+f"(d[0]), "+f"(d[1]), "+f"(d[2]), "+f"(d[3])
        : "r"(a[0]), "r"(a[1]), "r"(a[2]), "r"(a[3]), "r"(b0), "r"(b1));
}
__device__ __forceinline__ float elu_f(float x) {
    return x > 0.f ? x : (__expf(x) - 1.f);
}

// ---------------- prep 1: pack GEMM weights into per-lane B fragments ----------------
__global__ void prep_kernel(const float* __restrict__ ws_w, const float* __restrict__ wb1_w,
                            const float* __restrict__ wz_w, const float* __restrict__ wa1_w,
                            const float* __restrict__ wa2_w)
{
    int id = blockIdx.x * blockDim.x + threadIdx.x;
    if (id >= FRAG_TOTAL) return;
    const float* W; int N; int t, s;
    int l = id & 31;
    if (id < OFF_WB)       { W = ws_w;  N = 64; int loc = id;           t = loc >> 10; s = (loc >> 5) & 31; }
    else if (id < OFF_WZ)  { W = wb1_w; N = 64; int loc = id - OFF_WB;  t = loc >> 10; s = (loc >> 5) & 31; }
    else if (id < OFF_WA1) { W = wz_w;  N = 64; int loc = id - OFF_WZ;  t = loc >> 10; s = (loc >> 5) & 31; }
    else if (id < OFF_WA2) { W = wa1_w; N = 64; int loc = id - OFF_WA1; t = loc >> 8;  s = (loc >> 5) & 7;  }
    else                   { W = wa2_w; N = NF; int loc = id - OFF_WA2; t = loc >> 7;  s = (loc >> 5) & 3;  }
    int n = t * 8 + (l >> 2);
    int k = s * 16 + (l & 3) * 2;
    float v00 = W[(size_t)k * N + n],       v01 = W[(size_t)(k + 1) * N + n];
    float v10 = W[(size_t)(k + 8) * N + n], v11 = W[(size_t)(k + 9) * N + n];
    __nv_bfloat16 h00, l00, h01, l01, h10, l10, h11, l11;
    split1(v00, h00, l00); split1(v01, h01, l01);
    split1(v10, h10, l10); split1(v11, h11, l11);
    g_frag[id] = make_uint4(pack_bf2(h00, h01), pack_bf2(h10, h11),
                            pack_bf2(l00, l01), pack_bf2(l10, l11));
}

// ---------------- prep 2: transpose shape-fn weights (|w| applied) + pair table ----------------
__global__ void prep_shape_kernel(
    const float* __restrict__ w1_1, const float* __restrict__ b1_1,
    const float* __restrict__ w2_1, const float* __restrict__ b2_1,
    const float* __restrict__ w3_1, const float* __restrict__ b3_1,
    const float* __restrict__ w1_2, const float* __restrict__ b1_2,
    const float* __restrict__ w2_2, const float* __restrict__ b2_2,
    const float* __restrict__ w3_2, const float* __restrict__ b3_2)
{
    int id = blockIdx.x * blockDim.x + threadIdx.x;
    if (id < SH2_C * N2) {
        int c = id / N2, p = id % N2;
        float v;
        if (c < 16)      v = fabsf(w1_2[p * 16 + c]);
        else if (c < 24) v = b1_2[p * 8 + (c - 16)];
        else if (c < 56) v = fabsf(w2_2[p * 32 + (c - 24)]);
        else if (c < 60) v = b2_2[p * 4 + (c - 56)];
        else if (c < 64) v = fabsf(w3_2[p * 4 + (c - 60)]);
        else             v = b3_2[p];
        g_sh2[id] = v;
        return;
    }
    int id2 = id - SH2_C * N2;
    if (id2 < SH1_C * N1) {
        int c = id2 / N1, n = id2 % N1;
        float v;
        if (c < 8)       v = fabsf(w1_1[n * 8 + c]);
        else if (c < 16) v = b1_1[n * 8 + (c - 8)];
        else if (c < 48) v = fabsf(w2_1[n * 32 + (c - 16)]);
        else if (c < 52) v = b2_1[n * 4 + (c - 48)];
        else if (c < 56) v = fabsf(w3_1[n * 4 + (c - 52)]);
        else             v = b3_1[n];
        g_sh1[id2] = v;
        return;
    }
    int p = id2 - SH1_C * N1;
    if (p < N2) {
        int ii = 0, rem = p, cnt = NAG - 1;
        while (rem >= cnt) { rem -= cnt; cnt--; ii++; }
        g_pair[p] = make_int2(ii, ii + 1 + rem);
    }
}

// ---------------- main fused kernel ----------------
__global__ __launch_bounds__(THREADS, 3) void na2q_kernel(
    const float* __restrict__ q_in,   const float* __restrict__ state,  const float* __restrict__ sem,
    const float* __restrict__ ws_b,   const float* __restrict__ wz_b,
    const float* __restrict__ wa1_b,  const float* __restrict__ wa2_b,
    const float* __restrict__ wb1_b,  const float* __restrict__ wb2_w,
    const float* __restrict__ wb2_b,
    float* __restrict__ out_q, float* __restrict__ out_attn, float* __restrict__ out_shape)
{
    extern __shared__ char smem[];
    float* s_attn = (float*)smem;                 // [16][528] fp32, aliases x chunk buffers
    float* s_q    = (float*)(smem + QOFF);        // [16][32]
    float* s_bias = (float*)(smem + BOFF);        // [16]

    const int tid  = threadIdx.x;
    const int row0 = blockIdx.x * TB;
    const int warp = tid >> 5;
    const int lane = tid & 31;
    const int g    = lane >> 2;
    const int cp   = (lane & 3) * 2;

    const int grp  = lane >> 3;
    const int arow = (lane & 7) + ((grp & 1) << 3);
    const int akof = ((grp >> 1) << 3) * 2;
    const uint32_t sbase  = (uint32_t)__cvta_generic_to_shared(smem);
    const uint32_t aoff_x = arow * 528 + akof;
    const uint32_t aoff_c = arow * 272 + akof;
    const uint32_t aoff_a = arow * 144 + akof;

    for (int i = tid; i < TB * NAG; i += THREADS) s_q[i] = q_in[row0 * NAG + i];
    if (tid < TB) s_bias[tid] = wb2_b[0];

    // ===== encoders: state_enc / bias_hidden / sem_enc via 3-term bf16 mma =====
    float dws[4] = {0,0,0,0}, dwb[4] = {0,0,0,0}, dwz[4] = {0,0,0,0};
    for (int c = 0; c < 2; c++) {
        __syncthreads();
        for (int i = tid; i < 1024; i += THREADS) {
            int r = i >> 6, kq = i & 63;
            float4 v = *(const float4*)(state + (size_t)(row0 + r) * SDIM + c * 256 + kq * 4);
            __nv_bfloat16 h0,l0,h1,l1,h2,l2,h3,l3;
            split1(v.x,h0,l0); split1(v.y,h1,l1); split1(v.z,h2,l2); split1(v.w,h3,l3);
            *(uint2*)(smem + XS_H + r * 528 + kq * 8) = make_uint2(pack_bf2(h0,h1), pack_bf2(h2,h3));
            *(uint2*)(smem + XS_L + r * 528 + kq * 8) = make_uint2(pack_bf2(l0,l1), pack_bf2(l2,l3));
            v = *(const float4*)(sem + (size_t)(row0 + r) * SDIM + c * 256 + kq * 4);
            split1(v.x,h0,l0); split1(v.y,h1,l1); split1(v.z,h2,l2); split1(v.w,h3,l3);
            *(uint2*)(smem + XZ_H + r * 528 + kq * 8) = make_uint2(pack_bf2(h0,h1), pack_bf2(h2,h3));
            *(uint2*)(smem + XZ_L + r * 528 + kq * 8) = make_uint2(pack_bf2(l0,l1), pack_bf2(l2,l3));
        }
        __syncthreads();
        #pragma unroll 4
        for (int ks = 0; ks < 16; ks++) {
            int s = c * 16 + ks;
            uint32_t ah[4], al[4], zh[4], zl[4];
            ldm4(ah, sbase + XS_H + aoff_x + ks * 32);
            ldm4(al, sbase + XS_L + aoff_x + ks * 32);
            uint4 bws = g_frag[OFF_WS + (warp * NKS_ENC + s) * 32 + lane];
            uint4 bwb = g_frag[OFF_WB + (warp * NKS_ENC + s) * 32 + lane];
            mma16816(dws, ah, bws.x, bws.y);
            mma16816(dws, ah, bws.z, bws.w);
            mma16816(dws, al, bws.x, bws.y);
            mma16816(dwb, ah, bwb.x, bwb.y);
            mma16816(dwb, ah, bwb.z, bwb.w);
            mma16816(dwb, al, bwb.x, bwb.y);
            ldm4(zh, sbase + XZ_H + aoff_x + ks * 32);
            ldm4(zl, sbase + XZ_L + aoff_x + ks * 32);
            uint4 bwz = g_frag[OFF_WZ + (warp * NKS_ENC + s) * 32 + lane];
            mma16816(dwz, zh, bwz.x, bwz.y);
            mma16816(dwz, zh, bwz.z, bwz.w);
            mma16816(dwz, zl, bwz.x, bwz.y);
        }
    }
    {
        int c0c = 8 * warp + cp;
        float v; __nv_bfloat16 h, l;
        v = fmaxf(dws[0] + ws_b[c0c],   0.f); split1(v,h,l);
        *(__nv_bfloat16*)(smem + CMB_H + g*272 + c0c*2) = h;       *(__nv_bfloat16*)(smem + CMB_L + g*272 + c0c*2) = l;
        v = fmaxf(dws[1] + ws_b[c0c+1], 0.f); split1(v,h,l);
        *(__nv_bfloat16*)(smem + CMB_H + g*272 + (c0c+1)*2) = h;   *(__nv_bfloat16*)(smem + CMB_L + g*272 + (c0c+1)*2) = l;
        v = fmaxf(dws[2] + ws_b[c0c],   0.f); split1(v,h,l);
        *(__nv_bfloat16*)(smem + CMB_H + (g+8)*272 + c0c*2) = h;   *(__nv_bfloat16*)(smem + CMB_L + (g+8)*272 + c0c*2) = l;
        v = fmaxf(dws[3] + ws_b[c0c+1], 0.f); split1(v,h,l);
        *(__nv_bfloat16*)(smem + CMB_H + (g+8)*272 + (c0c+1)*2) = h; *(__nv_bfloat16*)(smem + CMB_L + (g+8)*272 + (c0c+1)*2) = l;

        int zc = 64 + c0c;
        v = fmaxf(dwz[0] + wz_b[c0c],   0.f); split1(v,h,l);
        *(__nv_bfloat16*)(smem + CMB_H + g*272 + zc*2) = h;        *(__nv_bfloat16*)(smem + CMB_L + g*272 + zc*2) = l;
        v = fmaxf(dwz[1] + wz_b[c0c+1], 0.f); split1(v,h,l);
        *(__nv_bfloat16*)(smem + CMB_H + g*272 + (zc+1)*2) = h;    *(__nv_bfloat16*)(smem + CMB_L + g*272 + (zc+1)*2) = l;
        v = fmaxf(dwz[2] + wz_b[c0c],   0.f); split1(v,h,l);
        *(__nv_bfloat16*)(smem + CMB_H + (g+8)*272 + zc*2) = h;    *(__nv_bfloat16*)(smem + CMB_L + (g+8)*272 + zc*2) = l;
        v = fmaxf(dwz[3] + wz_b[c0c+1], 0.f); split1(v,h,l);
        *(__nv_bfloat16*)(smem + CMB_H + (g+8)*272 + (zc+1)*2) = h; *(__nv_bfloat16*)(smem + CMB_L + (g+8)*272 + (zc+1)*2) = l;

        float hb0 = fmaxf(dwb[0] + wb1_b[c0c],   0.f) * wb2_w[c0c];
        float hb1 = fmaxf(dwb[1] + wb1_b[c0c+1], 0.f) * wb2_w[c0c+1];
        float hb2 = fmaxf(dwb[2] + wb1_b[c0c],   0.f) * wb2_w[c0c];
        float hb3 = fmaxf(dwb[3] + wb1_b[c0c+1], 0.f) * wb2_w[c0c+1];
        float p0 = hb0 + hb1, p1 = hb2 + hb3;
        p0 += __shfl_xor_sync(0xffffffffu, p0, 1); p0 += __shfl_xor_sync(0xffffffffu, p0, 2);
        p1 += __shfl_xor_sync(0xffffffffu, p1, 1); p1 += __shfl_xor_sync(0xffffffffu, p1, 2);
        if ((lane & 3) == 0) { atomicAdd(&s_bias[g], p0); atomicAdd(&s_bias[g + 8], p1); }
    }
    __syncthreads();

    // ===== stage D: a1 = relu(comb @ wa1 + b) =====
    {
        float da[4] = {0,0,0,0};
        #pragma unroll
        for (int s = 0; s < 8; s++) {
            uint32_t ch[4], cl[4];
            ldm4(ch, sbase + CMB_H + aoff_c + s * 32);
            ldm4(cl, sbase + CMB_L + aoff_c + s * 32);
            uint4 b = g_frag[OFF_WA1 + (warp * NKS_D + s) * 32 + lane];
            mma16816(da, ch, b.x, b.y);
            mma16816(da, ch, b.z, b.w);
            mma16816(da, cl, b.x, b.y);
        }
        int ca = 8 * warp + cp;
        float v; __nv_bfloat16 h, l;
        v = fmaxf(da[0] + wa1_b[ca],   0.f); split1(v,h,l);
        *(__nv_bfloat16*)(smem + A1_H + g*144 + ca*2) = h;        *(__nv_bfloat16*)(smem + A1_L + g*144 + ca*2) = l;
        v = fmaxf(da[1] + wa1_b[ca+1], 0.f); split1(v,h,l);
        *(__nv_bfloat16*)(smem + A1_H + g*144 + (ca+1)*2) = h;    *(__nv_bfloat16*)(smem + A1_L + g*144 + (ca+1)*2) = l;
        v = fmaxf(da[2] + wa1_b[ca],   0.f); split1(v,h,l);
        *(__nv_bfloat16*)(smem + A1_H + (g+8)*144 + ca*2) = h;    *(__nv_bfloat16*)(smem + A1_L + (g+8)*144 + ca*2) = l;
        v = fmaxf(da[3] + wa1_b[ca+1], 0.f); split1(v,h,l);
        *(__nv_bfloat16*)(smem + A1_H + (g+8)*144 + (ca+1)*2) = h; *(__nv_bfloat16*)(smem + A1_L + (g+8)*144 + (ca+1)*2) = l;
    }
    __syncthreads();

    // ===== stage E: logits = a1 @ wa2 + b =====
    {
        uint32_t eh[4][4], el[4][4];
        #pragma unroll
        for (int s = 0; s < 4; s++) {
            ldm4(eh[s], sbase + A1_H + aoff_a + s * 32);
            ldm4(el[s], sbase + A1_L + aoff_a + s * 32);
        }
        for (int t = warp; t < NT_E; t += 8) {
            float d[4] = {0,0,0,0};
            #pragma unroll
            for (int s = 0; s < 4; s++) {
                uint4 b = g_frag[OFF_WA2 + (t * NKS_E + s) * 32 + lane];
                mma16816(d, eh[s], b.x, b.y);
                mma16816(d, eh[s], b.z, b.w);
                mma16816(d, el[s], b.x, b.y);
            }
            int fc = 8 * t + cp;
            s_attn[g * NF + fc]           = d[0] + wa2_b[fc];
            s_attn[g * NF + fc + 1]       = d[1] + wa2_b[fc + 1];
            s_attn[(g + 8) * NF + fc]     = d[2] + wa2_b[fc];
            s_attn[(g + 8) * NF + fc + 1] = d[3] + wa2_b[fc + 1];
        }
    }
    __syncthreads();

    // ===== stage F: softmax per row =====
    for (int r = warp; r < TB; r += THREADS / 32) {
        float mx = -1e30f;
        for (int f = lane; f < NF; f += 32) mx = fmaxf(mx, s_attn[r * NF + f]);
        #pragma unroll
        for (int o = 16; o; o >>= 1) mx = fmaxf(mx, __shfl_xor_sync(0xffffffffu, mx, o));
        float sum = 0.f;
        for (int f = lane; f < NF; f += 32) {
            float e = __expf(s_attn[r * NF + f] - mx);
            s_attn[r * NF + f] = e;
            sum += e;
        }
        #pragma unroll
        for (int o = 16; o; o >>= 1) sum += __shfl_xor_sync(0xffffffffu, sum, o);
        float inv = 1.f / sum;
        for (int f = lane; f < NF; f += 32) {
            float a = s_attn[r * NF + f] * inv;
            s_attn[r * NF + f] = a;
            out_attn[(size_t)(row0 + r) * NF + f] = a;
        }
    }
    __syncthreads();

    // ===== stage G: shape fns (transposed coalesced weights); s_attn *= shape =====
    for (int f = tid; f < NF; f += THREADS) {
        if (f < N1) {
            const float* Wt = g_sh1 + f;
            float w1[8], b1[8], w2[32], b2v[4], w3[4];
            #pragma unroll
            for (int j = 0; j < 8; j++)  w1[j]  = Wt[j * N1];
            #pragma unroll
            for (int j = 0; j < 8; j++)  b1[j]  = Wt[(8 + j) * N1];
            #pragma unroll
            for (int j = 0; j < 32; j++) w2[j]  = Wt[(16 + j) * N1];
            #pragma unroll
            for (int j = 0; j < 4; j++)  b2v[j] = Wt[(48 + j) * N1];
            #pragma unroll
            for (int j = 0; j < 4; j++)  w3[j]  = Wt[(52 + j) * N1];
            float b3v = Wt[56 * N1];
            for (int r = 0; r < TB; r++) {
                float x = s_q[r * NAG + f];
                float h1[8];
                #pragma unroll
                for (int j = 0; j < 8; j++) h1[j] = elu_f(fmaf(x, w1[j], b1[j]));
                float outv = b3v;
                #pragma unroll
                for (int j = 0; j < 4; j++) {
                    float a = b2v[j];
                    #pragma unroll
                    for (int k = 0; k < 8; k++) a = fmaf(h1[k], w2[k * 4 + j], a);
                    outv = fmaf(elu_f(a), w3[j], outv);
                }
                out_shape[(size_t)(row0 + r) * NF + f] = outv;
                s_attn[r * NF + f] *= outv;
            }
        } else {
            int p = f - N1;
            int2 ij = g_pair[p];
            const float* Wt = g_sh2 + p;
            float w1[16], b1[8], w2[32], b2v[4], w3[4];
            #pragma unroll
            for (int j = 0; j < 16; j++) w1[j]  = Wt[j * N2];
            #pragma unroll
            for (int j = 0; j < 8; j++)  b1[j]  = Wt[(16 + j) * N2];
            #pragma unroll
            for (int j = 0; j < 32; j++) w2[j]  = Wt[(24 + j) * N2];
            #pragma unroll
            for (int j = 0; j < 4; j++)  b2v[j] = Wt[(56 + j) * N2];
            #pragma unroll
            for (int j = 0; j < 4; j++)  w3[j]  = Wt[(60 + j) * N2];
            float b3v = Wt[64 * N2];
            for (int r = 0; r < TB; r++) {
                float xi = s_q[r * NAG + ij.x];
                float xj = s_q[r * NAG + ij.y];
                float h1[8];
                #pragma unroll
                for (int j = 0; j < 8; j++)
                    h1[j] = elu_f(fmaf(xj, w1[8 + j], fmaf(xi, w1[j], b1[j])));
                float outv = b3v;
                #pragma unroll
                for (int j = 0; j < 4; j++) {
                    float a = b2v[j];
                    #pragma unroll
                    for (int k = 0; k < 8; k++) a = fmaf(h1[k], w2[k * 4 + j], a);
                    outv = fmaf(elu_f(a), w3[j], outv);
                }
                out_shape[(size_t)(row0 + r) * NF + f] = outv;
                s_attn[r * NF + f] *= outv;
            }
        }
    }
    __syncthreads();

    // ===== stage H: q_total =====
    for (int r = warp; r < TB; r += THREADS / 32) {
        float acc = 0.f;
        for (int f = lane; f < NF; f += 32) acc += s_attn[r * NF + f];
        #pragma unroll
        for (int o = 16; o; o >>= 1) acc += __shfl_xor_sync(0xffffffffu, acc, o);
        if (lane == 0) out_q[row0 + r] = acc + s_bias[r];
    }
}

extern "C" void kernel_launch(void* const* d_in, const int* in_sizes, int n_in,
                              void* d_out, int out_size)
{
    const float* A[27];
    for (int i = 0; i < 27; i++) A[i] = (const float*)d_in[i];
    int Btot = in_sizes[0] / NAG;

    float* out       = (float*)d_out;
    float* out_q     = out;
    float* out_attn  = out + Btot;
    float* out_shape = out + Btot + (size_t)Btot * NF;

    prep_kernel<<<(FRAG_TOTAL + 255) / 256, 256>>>(A[15], A[23], A[17], A[19], A[21]);
    int shape_threads = SH2_C * N2 + SH1_C * N1 + N2;
    prep_shape_kernel<<<(shape_threads + 255) / 256, 256>>>(
        A[3], A[4], A[5], A[6], A[7], A[8],
        A[9], A[10], A[11], A[12], A[13], A[14]);

    cudaFuncSetAttribute(na2q_kernel, cudaFuncAttributeMaxDynamicSharedMemorySize, SMEM_TOTAL);
    na2q_kernel<<<Btot / TB, THREADS, SMEM_TOTAL>>>(
        A[0], A[1], A[2],
        A[16], A[18],        // ws_b, wz_b
        A[20], A[22],        // wa1_b, wa2_b
        A[24], A[25], A[26], // wb1_b, wb2_w, wb2_b
        out_q, out_attn, out_shape);
}